// round 5
// baseline (speedup 1.0000x reference)
#include <cuda_runtime.h>
#include <math_constants.h>

// ---------------------------------------------------------------------------
// NeuralSpectralBlock2D  (B=16, C=64, H=W=240, P=3, HEAD=8, dh=8, T=4, M=12)
// One warp = one patch; CTA = 256 threads = 8 patches. Single fused channel
// loop (25 packed f32x2 FMA). Weights pre-DUPLICATED into pair form in global
// memory so the loop has zero splat MOVs: 3 LDG + 3 LDS + 25 FFMA2 per ch.
// ---------------------------------------------------------------------------

#define Bn    16
#define Cn    64
#define Hn    240
#define Wn    240
#define NP    8           // patches per CTA
#define NT    256         // threads per CTA (8 warps)

#define HPn   80
#define WPn   80
#define WBLK  (WPn / NP)          // 10
#define GRID  (Bn * HPn * WBLK)   // 12800

// per-channel duplicated-weight record: 320 floats
//   [c*320 + 2*lane]        {a,a}
//   [c*320 + 64 + 4*lane]   {w0,w0,w1,w1}
//   [c*320 + 192 + 4*lane]  {d0,d0,d1,d1}
#define WREC  320
#define WDUP_F (64 * WREC)        // 20480 floats = 80KB

// small-const block offsets (smem copy)
#define S_C1  0          // c1[ht]        32
#define S_BV  32         // bv[hd]        64
#define S_BD  96         // bd[o]         64
#define S_WT  160        // wt[m'][c]     1536
#define S_Q   1696       // q[hd][t]      256
#define S_SZ  1952

// ---- shared layout (floats) ----
#define XPS   776        // per-patch xp stride ([c*12 + pos], pos 0..9, 9=0)
#define XQS   640        // xq/xo [ch*10+pos]
#define LTS   320        // lt' [ch*5+t]; attn1 [ht*9+pos] overlaid (288<=320)
#define SM_XP (S_SZ)
#define SM_XQ (SM_XP + NP*XPS)
#define SM_LT (SM_XQ + NP*XQS)
#define SMEM_F (SM_LT + NP*LTS)
#define SMEM_B (SMEM_F * 4)       // 63360 bytes

__device__ __align__(16) float g_wdup[WDUP_F];
__device__ __align__(16) float g_small[S_SZ];

typedef unsigned long long ull;

// ---------------- f32x2 helpers ----------------
__device__ __forceinline__ ull ffma2(ull a, ull b, ull c) {
    ull d;
    asm("fma.rn.f32x2 %0, %1, %2, %3;" : "=l"(d) : "l"(a), "l"(b), "l"(c));
    return d;
}
__device__ __forceinline__ ull splat2(float x) {
    ull r;
    unsigned u = __float_as_uint(x);
    asm("mov.b64 %0, {%1, %1};" : "=l"(r) : "r"(u));
    return r;
}
__device__ __forceinline__ float2 unpack2(ull v) {
    float lo, hi;
    asm("mov.b64 {%0, %1}, %2;" : "=f"(lo), "=f"(hi) : "l"(v));
    return make_float2(lo, hi);
}

// ---------------- setup: fold + duplicate constants ----------------
__global__ void setup_kernel(const float* __restrict__ latent,
                             const float* __restrict__ weights,
                             const float* __restrict__ enc_w,
                             const float* __restrict__ enc_b,
                             const float* __restrict__ dec_w,
                             const float* __restrict__ dec_b) {
    int tid = threadIdx.x;
    // per (c, lane): A fold + WV + WD, duplicated into pair form
    for (int i = tid; i < 2048; i += 256) {
        int c = i >> 5, lane = i & 31;
        // a = A[c][lane] where lane = ht  (h = lane>>2, t = lane&3)
        int h = lane >> 2, t = lane & 3;
        float a = 0.f;
        for (int d = 0; d < 8; d++)
            a += latent[h * 32 + t * 8 + d] * enc_w[(h * 16 + 2 * d) * 64 + c];
        g_wdup[c * WREC + 2 * lane + 0] = a;
        g_wdup[c * WREC + 2 * lane + 1] = a;
        // wv pair for channels lane, lane+32
        int h0 = lane >> 3, d0 = lane & 7;
        int l1 = lane + 32, h1 = l1 >> 3, d1 = l1 & 7;
        float w0 = enc_w[(h0 * 16 + 2 * d0 + 1) * 64 + c];
        float w1 = enc_w[(h1 * 16 + 2 * d1 + 1) * 64 + c];
        g_wdup[c * WREC + 64 + 4 * lane + 0] = w0;
        g_wdup[c * WREC + 64 + 4 * lane + 1] = w0;
        g_wdup[c * WREC + 64 + 4 * lane + 2] = w1;
        g_wdup[c * WREC + 64 + 4 * lane + 3] = w1;
        float e0 = dec_w[lane * 64 + c];
        float e1 = dec_w[l1 * 64 + c];
        g_wdup[c * WREC + 192 + 4 * lane + 0] = e0;
        g_wdup[c * WREC + 192 + 4 * lane + 1] = e0;
        g_wdup[c * WREC + 192 + 4 * lane + 2] = e1;
        g_wdup[c * WREC + 192 + 4 * lane + 3] = e1;
    }
    // small block
    for (int i = tid; i < 32; i += 256) {           // c1
        int h = i >> 2, t = i & 3;
        float s = 0.f;
        for (int d = 0; d < 8; d++)
            s += latent[h * 32 + t * 8 + d] * enc_b[h * 16 + 2 * d];
        g_small[S_C1 + i] = s;
    }
    for (int i = tid; i < 64; i += 256) {           // bv, bd
        int h = i >> 3, d = i & 7;
        g_small[S_BV + i] = enc_b[h * 16 + 2 * d + 1];
        g_small[S_BD + i] = dec_b[i];
    }
    for (int i = tid; i < 1536; i += 256) {         // wt[m'][c]
        int m = i >> 6, c = i & 63;
        g_small[S_WT + i] = weights[c * 24 + m];
    }
    for (int i = tid; i < 256; i += 256) {          // q[hd][t]
        int hd = i >> 2, t = i & 3;
        int h = hd >> 3, d = hd & 7;
        g_small[S_Q + i] = latent[h * 32 + t * 8 + d];
    }
}

// ---------------- main fused kernel ----------------
__global__ void __launch_bounds__(NT, 3)
nsb_kernel(const float* __restrict__ x, float* __restrict__ out) {
    extern __shared__ float sm[];
    float* ss  = sm;             // small consts
    float* sxp = sm + SM_XP;
    float* sxq = sm + SM_XQ;
    float* slt = sm + SM_LT;

    const int tid = threadIdx.x;

    // small consts -> smem
    for (int i = tid; i < S_SZ; i += NT) ss[i] = g_small[i];

    // zero-pad position 9 of every (patch, channel) row
    for (int i = tid; i < NP * 64; i += NT)
        sxp[(i >> 6) * XPS + (i & 63) * 12 + 9] = 0.f;

    // CTA -> (b, hp, wblk)
    const int cta  = blockIdx.x;
    const int wblk = cta % WBLK;
    const int hp   = (cta / WBLK) % HPn;
    const int b    = cta / (WBLK * HPn);

    // cooperative patchify load: 64 ch x 3 rows x 24 cols
    for (int i = tid; i < 64 * 3 * 24; i += NT) {
        int col = i % 24;
        int seg = i / 24;
        int p0  = seg % 3;
        int c   = seg / 3;
        int wl  = col / 3, p1 = col % 3;
        float v = x[((b * 64 + c) * Hn + hp * 3 + p0) * Wn + wblk * 24 + col];
        sxp[wl * XPS + c * 12 + p0 * 3 + p1] = v;
    }
    __syncthreads();

    const int warp = tid >> 5;
    const int lane = tid & 31;
    float* xp = sxp + warp * XPS;
    float* xq = sxq + warp * XQS;
    float* lp = slt + warp * LTS;
    float* at = lp;               // attn1 overlaid on lp (disjoint lifetimes)

    // ========== single fused channel loop: scores1 + v + dec =========
    ull s1p[5], v0p[5], v1p[5], u0p[5], u1p[5];
    {
        ull c1s = splat2(ss[S_C1 + lane]);
        ull b0s = splat2(ss[S_BV + lane]);
        ull b1s = splat2(ss[S_BV + lane + 32]);
        ull e0s = splat2(ss[S_BD + lane]);
        ull e1s = splat2(ss[S_BD + lane + 32]);
#pragma unroll
        for (int j = 0; j < 5; j++) {
            s1p[j] = c1s; v0p[j] = b0s; v1p[j] = b1s; u0p[j] = e0s; u1p[j] = e1s;
        }
    }
    {
        const float* gw = g_wdup;
        const float* xr = xp;
#pragma unroll 2
        for (int c = 0; c < 64; c++) {
            ull        ap  = __ldg((const ull*)(gw + 2 * lane));
            ulonglong2 wvp = __ldg((const ulonglong2*)(gw + 64 + 4 * lane));
            ulonglong2 wdp = __ldg((const ulonglong2*)(gw + 192 + 4 * lane));
            ull w0p = wvp.x, w1p = wvp.y, d0p = wdp.x, d1p = wdp.y;
            ulonglong2 xa = *(const ulonglong2*)xr;        // pos 0-3
            ulonglong2 xb = *(const ulonglong2*)(xr + 4);  // pos 4-7
            ull        xc = *(const ull*)(xr + 8);         // pos 8, 9(=0)
            ull xx0 = xa.x, xx1 = xa.y, xx2 = xb.x, xx3 = xb.y, xx4 = xc;
            s1p[0] = ffma2(ap, xx0, s1p[0]); s1p[1] = ffma2(ap, xx1, s1p[1]);
            s1p[2] = ffma2(ap, xx2, s1p[2]); s1p[3] = ffma2(ap, xx3, s1p[3]);
            s1p[4] = ffma2(ap, xx4, s1p[4]);
            v0p[0] = ffma2(w0p, xx0, v0p[0]); v0p[1] = ffma2(w0p, xx1, v0p[1]);
            v0p[2] = ffma2(w0p, xx2, v0p[2]); v0p[3] = ffma2(w0p, xx3, v0p[3]);
            v0p[4] = ffma2(w0p, xx4, v0p[4]);
            v1p[0] = ffma2(w1p, xx0, v1p[0]); v1p[1] = ffma2(w1p, xx1, v1p[1]);
            v1p[2] = ffma2(w1p, xx2, v1p[2]); v1p[3] = ffma2(w1p, xx3, v1p[3]);
            v1p[4] = ffma2(w1p, xx4, v1p[4]);
            u0p[0] = ffma2(d0p, xx0, u0p[0]); u0p[1] = ffma2(d0p, xx1, u0p[1]);
            u0p[2] = ffma2(d0p, xx2, u0p[2]); u0p[3] = ffma2(d0p, xx3, u0p[3]);
            u0p[4] = ffma2(d0p, xx4, u0p[4]);
            u1p[0] = ffma2(d1p, xx0, u1p[0]); u1p[1] = ffma2(d1p, xx1, u1p[1]);
            u1p[2] = ffma2(d1p, xx2, u1p[2]); u1p[3] = ffma2(d1p, xx3, u1p[3]);
            u1p[4] = ffma2(d1p, xx4, u1p[4]);
            gw += WREC;
            xr += 12;
        }
    }

    // unpack scores1 and v; stash xq rows to shared (pairs are contiguous)
    float s1[9], v0[9], v1[9];
#pragma unroll
    for (int j = 0; j < 4; j++) {
        float2 f;
        f = unpack2(s1p[j]); s1[2 * j] = f.x; s1[2 * j + 1] = f.y;
        f = unpack2(v0p[j]); v0[2 * j] = f.x; v0[2 * j + 1] = f.y;
        f = unpack2(v1p[j]); v1[2 * j] = f.x; v1[2 * j + 1] = f.y;
    }
    s1[8] = unpack2(s1p[4]).x;
    v0[8] = unpack2(v0p[4]).x;
    v1[8] = unpack2(v1p[4]).x;
    {
        ull* q0 = (ull*)(xq + lane * 10);
        ull* q1 = (ull*)(xq + (lane + 32) * 10);
#pragma unroll
        for (int j = 0; j < 5; j++) { q0[j] = u0p[j]; q1[j] = u1p[j]; }
    }

    // softmax over pos (lane = ht) -> attn1 to shared (at == lp region)
    {
        float mx = s1[0];
#pragma unroll
        for (int p = 1; p < 9; p++) mx = fmaxf(mx, s1[p]);
        float sum = 0.f;
#pragma unroll
        for (int p = 0; p < 9; p++) { s1[p] = __expf(s1[p] - mx); sum += s1[p]; }
        float inv = 1.0f / sum;
#pragma unroll
        for (int p = 0; p < 9; p++) at[lane * 9 + p] = s1[p] * inv;
    }
    __syncwarp();

    // lt[h,t,d] = attn1 @ v + q   (lane owns channels lane, lane+32)
    const int h0 = lane >> 3;
    float lt0[4], lt1[4];
#pragma unroll
    for (int t = 0; t < 4; t++) {
        float a0 = ss[S_Q + lane * 4 + t];
        float a1 = ss[S_Q + (lane + 32) * 4 + t];
        const float* r0 = at + (h0 * 4 + t) * 9;
        const float* r1 = at + ((h0 + 4) * 4 + t) * 9;
#pragma unroll
        for (int p = 0; p < 9; p++) {
            a0 = fmaf(r0[p], v0[p], a0);
            a1 = fmaf(r1[p], v1[p], a1);
        }
        lt0[t] = a0; lt1[t] = a1;
    }
    __syncwarp();     // all lanes done reading attn1 before lp overwrite

    // spectral basis mixing via angle-addition recurrence -> lp[ch*5+t]
#pragma unroll
    for (int t = 0; t < 4; t++) {
        float base0 = lt0[t] * (float)(CUDART_PI / 12.0);
        float base1 = lt1[t] * (float)(CUDART_PI / 12.0);
        float s0, c0, sB, cB;
        __sincosf(base0, &s0, &c0);
        __sincosf(base1, &sB, &cB);
        float acc0 = ss[S_WT + 12 * 64 + lane];        // m=0: sin=0, cos=1
        float acc1 = ss[S_WT + 12 * 64 + lane + 32];
        float sa = s0, ca = c0, sb = sB, cb = cB;
#pragma unroll
        for (int m = 1; m < 12; m++) {
            acc0 = fmaf(sa, ss[S_WT + m * 64 + lane],
                   fmaf(ca, ss[S_WT + (12 + m) * 64 + lane], acc0));
            acc1 = fmaf(sb, ss[S_WT + m * 64 + lane + 32],
                   fmaf(cb, ss[S_WT + (12 + m) * 64 + lane + 32], acc1));
            float ns = fmaf(sa, c0,  ca * s0);
            float nc = fmaf(ca, c0, -sa * s0);
            sa = ns; ca = nc;
            float ms = fmaf(sb, cB,  cb * sB);
            float mc = fmaf(cb, cB, -sb * sB);
            sb = ms; cb = mc;
        }
        lp[lane * 5 + t]        = lt0[t] + acc0;
        lp[(lane + 32) * 5 + t] = lt1[t] + acc1;
    }
    __syncwarp();

    // ========= decoder attention (72 items = h x pos) =========
#pragma unroll
    for (int k = 0; k < 3; k++) {
        int item = lane + 32 * k;
        if (item < 72) {
            int h = item / 9, pos = item - h * 9;
            float sc[4] = {0.f, 0.f, 0.f, 0.f};
#pragma unroll
            for (int d = 0; d < 8; d++) {
                float xv = xq[(h * 8 + d) * 10 + pos];
                const float* lr = lp + (h * 8 + d) * 5;
#pragma unroll
                for (int t = 0; t < 4; t++) sc[t] = fmaf(xv, lr[t], sc[t]);
            }
            float m2 = fmaxf(fmaxf(sc[0], sc[1]), fmaxf(sc[2], sc[3]));
            float es = 0.f;
#pragma unroll
            for (int t = 0; t < 4; t++) { sc[t] = __expf(sc[t] - m2); es += sc[t]; }
            float inv = 1.0f / es;
#pragma unroll
            for (int t = 0; t < 4; t++) sc[t] *= inv;
#pragma unroll
            for (int d = 0; d < 8; d++) {
                const float* lr = lp + (h * 8 + d) * 5;
                float o = 0.f;
#pragma unroll
                for (int t = 0; t < 4; t++) o = fmaf(sc[t], lr[t], o);
                xq[(h * 8 + d) * 10 + pos] = o;   // own (h,pos) slots only
            }
        }
    }
    __syncthreads();

    // cooperative un-patchify store with residual
    for (int i = tid; i < 64 * 3 * 24; i += NT) {
        int col = i % 24;
        int seg = i / 24;
        int p0  = seg % 3;
        int c   = seg / 3;
        int wl  = col / 3, p1 = col % 3;
        int pos = p0 * 3 + p1;
        out[((b * 64 + c) * Hn + hp * 3 + p0) * Wn + wblk * 24 + col] =
            sxq[wl * XQS + c * 10 + pos] + sxp[wl * XPS + c * 12 + pos];
    }
}

extern "C" void kernel_launch(void* const* d_in, const int* in_sizes, int n_in,
                              void* d_out, int out_size) {
    const float* x       = (const float*)d_in[0];
    const float* latent  = (const float*)d_in[1];
    const float* weights = (const float*)d_in[2];
    const float* enc_w   = (const float*)d_in[3];
    const float* enc_b   = (const float*)d_in[4];
    const float* dec_w   = (const float*)d_in[5];
    const float* dec_b   = (const float*)d_in[6];
    float* out = (float*)d_out;

    cudaFuncSetAttribute(nsb_kernel,
                         cudaFuncAttributeMaxDynamicSharedMemorySize, SMEM_B);

    setup_kernel<<<1, 256>>>(latent, weights, enc_w, enc_b, dec_w, dec_b);
    nsb_kernel<<<GRID, NT, SMEM_B>>>(x, out);
}

// round 6
// speedup vs baseline: 1.6944x; 1.6944x over previous
#include <cuda_runtime.h>
#include <math_constants.h>

// ---------------------------------------------------------------------------
// NeuralSpectralBlock2D  (B=16, C=64, H=W=240, P=3, HEAD=8, dh=8, T=4, M=12)
// One warp = one patch; CTA = 256 threads = 8 patches. Weights (40KB folded)
// live in SHARED memory per CTA -> hot loop is LDS-only (no L2 latency).
// 25 packed f32x2 FMA per channel. 2 CTAs/SM.
// ---------------------------------------------------------------------------

#define Bn    16
#define Cn    64
#define Hn    240
#define Wn    240
#define NP    8           // patches per CTA
#define NT    256         // threads per CTA (8 warps)

#define HPn   80
#define WPn   80
#define WBLK  (WPn / NP)          // 10
#define GRID  (Bn * HPn * WBLK)   // 12800

// ---- weight block (folded, non-duplicated): 10240 floats = 40KB ----
#define W_A   0          // A[c*32+lane]            2048
#define W_WV  2048       // WV float2 [c*32+lane]   4096
#define W_WD  6144       // WD float2 [c*32+lane]   4096
#define W_SZ  10240

// small-const block offsets
#define S_C1  0          // c1[ht]        32
#define S_BV  32         // bv[hd]        64
#define S_BD  96         // bd[o]         64
#define S_WT  160        // wt[m'][c]     1536
#define S_Q   1696       // q[hd][t]      256
#define S_SZ  1952

// ---- shared layout (floats) ----
#define XPS   776        // per-patch xp stride ([c*12 + pos], pos 0..9, 9=0)
#define XQS   640        // xq/xo [ch*10+pos]
#define LTS   320        // lt' [ch*5+t]; attn1 [ht*9+pos] overlaid (288<=320)
#define SM_S  (W_SZ)                  // small consts after weights
#define SM_XP (SM_S + S_SZ)
#define SM_XQ (SM_XP + NP*XPS)
#define SM_LT (SM_XQ + NP*XQS)
#define SMEM_F (SM_LT + NP*LTS)      // 26080 floats
#define SMEM_B (SMEM_F * 4)          // 104320 bytes

__device__ __align__(16) float g_wfold[W_SZ];
__device__ __align__(16) float g_small[S_SZ];

typedef unsigned long long ull;

// ---------------- f32x2 helpers ----------------
__device__ __forceinline__ ull ffma2(ull a, ull b, ull c) {
    ull d;
    asm("fma.rn.f32x2 %0, %1, %2, %3;" : "=l"(d) : "l"(a), "l"(b), "l"(c));
    return d;
}
__device__ __forceinline__ ull splat2(float x) {
    ull r;
    unsigned u = __float_as_uint(x);
    asm("mov.b64 %0, {%1, %1};" : "=l"(r) : "r"(u));
    return r;
}
__device__ __forceinline__ float2 unpack2(ull v) {
    float lo, hi;
    asm("mov.b64 {%0, %1}, %2;" : "=f"(lo), "=f"(hi) : "l"(v));
    return make_float2(lo, hi);
}

// ---------------- setup: fold constants ----------------
__global__ void setup_kernel(const float* __restrict__ latent,
                             const float* __restrict__ weights,
                             const float* __restrict__ enc_w,
                             const float* __restrict__ enc_b,
                             const float* __restrict__ dec_w,
                             const float* __restrict__ dec_b) {
    int tid = threadIdx.x;
    for (int i = tid; i < 2048; i += 256) {
        int c = i >> 5, lane = i & 31;
        // A fold: lane = ht
        int h = lane >> 2, t = lane & 3;
        float a = 0.f;
        for (int d = 0; d < 8; d++)
            a += latent[h * 32 + t * 8 + d] * enc_w[(h * 16 + 2 * d) * 64 + c];
        g_wfold[W_A + i] = a;
        // WV / WD pairs for channels lane, lane+32
        int h0 = lane >> 3, d0 = lane & 7;
        int l1 = lane + 32, h1 = l1 >> 3, d1 = l1 & 7;
        g_wfold[W_WV + 2 * i + 0] = enc_w[(h0 * 16 + 2 * d0 + 1) * 64 + c];
        g_wfold[W_WV + 2 * i + 1] = enc_w[(h1 * 16 + 2 * d1 + 1) * 64 + c];
        g_wfold[W_WD + 2 * i + 0] = dec_w[lane * 64 + c];
        g_wfold[W_WD + 2 * i + 1] = dec_w[l1 * 64 + c];
    }
    // small block
    for (int i = tid; i < 32; i += 256) {           // c1
        int h = i >> 2, t = i & 3;
        float s = 0.f;
        for (int d = 0; d < 8; d++)
            s += latent[h * 32 + t * 8 + d] * enc_b[h * 16 + 2 * d];
        g_small[S_C1 + i] = s;
    }
    for (int i = tid; i < 64; i += 256) {           // bv, bd
        int h = i >> 3, d = i & 7;
        g_small[S_BV + i] = enc_b[h * 16 + 2 * d + 1];
        g_small[S_BD + i] = dec_b[i];
    }
    for (int i = tid; i < 1536; i += 256) {         // wt[m'][c]
        int m = i >> 6, c = i & 63;
        g_small[S_WT + i] = weights[c * 24 + m];
    }
    for (int i = tid; i < 256; i += 256) {          // q[hd][t]
        int hd = i >> 2, t = i & 3;
        int h = hd >> 3, d = hd & 7;
        g_small[S_Q + i] = latent[h * 32 + t * 8 + d];
    }
}

// ---------------- main fused kernel ----------------
__global__ void __launch_bounds__(NT, 2)
nsb_kernel(const float* __restrict__ x, float* __restrict__ out) {
    extern __shared__ float sm[];
    float* sw  = sm;             // weights (40KB)
    float* ss  = sm + SM_S;      // small consts
    float* sxp = sm + SM_XP;
    float* sxq = sm + SM_XQ;
    float* slt = sm + SM_LT;

    const int tid = threadIdx.x;

    // weights -> smem (vectorized, coalesced; L2-resident source)
    {
        const float4* src = (const float4*)g_wfold;
        float4* dst = (float4*)sw;
#pragma unroll
        for (int i = 0; i < W_SZ / 4 / NT; i++)     // 10 iterations
            dst[tid + i * NT] = src[tid + i * NT];
    }
    // small consts -> smem
    for (int i = tid; i < S_SZ; i += NT) ss[i] = g_small[i];

    // zero-pad position 9 of every (patch, channel) row
    for (int i = tid; i < NP * 64; i += NT)
        sxp[(i >> 6) * XPS + (i & 63) * 12 + 9] = 0.f;

    // CTA -> (b, hp, wblk)
    const int cta  = blockIdx.x;
    const int wblk = cta % WBLK;
    const int hp   = (cta / WBLK) % HPn;
    const int b    = cta / (WBLK * HPn);

    // strength-reduced patchify mapping: thread owns fixed (col, p0, cgrp)
    const int col = tid % 24;
    const int rem = tid / 24;        // 0..10
    const int p0m = rem % 3;
    const int cg  = rem / 3;         // active if < 3
    const int wl  = col / 3;
    const int p1m = col - wl * 3;

    if (cg < 3) {
        const float* src = x + ((size_t)(b * 64 + cg) * Hn + hp * 3 + p0m) * Wn
                             + wblk * 24 + col;
        float* dst = sxp + wl * XPS + cg * 12 + p0m * 3 + p1m;
#pragma unroll
        for (int c = cg; c < 64; c += 3) {
            *dst = *src;
            src += 3 * Hn * Wn;
            dst += 36;
        }
    }
    __syncthreads();

    const int warp = tid >> 5;
    const int lane = tid & 31;
    float* xp = sxp + warp * XPS;
    float* xq = sxq + warp * XQS;
    float* lp = slt + warp * LTS;
    float* at = lp;               // attn1 overlaid on lp (disjoint lifetimes)

    const float*  wA = sw + W_A;
    const float2* wV = (const float2*)(sw + W_WV);
    const float2* wD = (const float2*)(sw + W_WD);

    // ========== single fused channel loop: scores1 + v + dec =========
    ull s1p[5], v0p[5], v1p[5], u0p[5], u1p[5];
    {
        ull c1s = splat2(ss[S_C1 + lane]);
        ull b0s = splat2(ss[S_BV + lane]);
        ull b1s = splat2(ss[S_BV + lane + 32]);
        ull e0s = splat2(ss[S_BD + lane]);
        ull e1s = splat2(ss[S_BD + lane + 32]);
#pragma unroll
        for (int j = 0; j < 5; j++) {
            s1p[j] = c1s; v0p[j] = b0s; v1p[j] = b1s; u0p[j] = e0s; u1p[j] = e1s;
        }
    }
#pragma unroll 2
    for (int c = 0; c < 64; c++) {
        float  a  = wA[c * 32 + lane];
        float2 wv = wV[c * 32 + lane];
        float2 wd = wD[c * 32 + lane];
        ull ap  = splat2(a);
        ull w0p = splat2(wv.x), w1p = splat2(wv.y);
        ull d0p = splat2(wd.x), d1p = splat2(wd.y);
        const float* xr = xp + c * 12;
        ulonglong2 xa = *(const ulonglong2*)xr;        // pos 0-3 (broadcast)
        ulonglong2 xb = *(const ulonglong2*)(xr + 4);  // pos 4-7
        ull        xc = *(const ull*)(xr + 8);         // pos 8, 9(=0)
        ull xx0 = xa.x, xx1 = xa.y, xx2 = xb.x, xx3 = xb.y, xx4 = xc;
        s1p[0] = ffma2(ap, xx0, s1p[0]); s1p[1] = ffma2(ap, xx1, s1p[1]);
        s1p[2] = ffma2(ap, xx2, s1p[2]); s1p[3] = ffma2(ap, xx3, s1p[3]);
        s1p[4] = ffma2(ap, xx4, s1p[4]);
        v0p[0] = ffma2(w0p, xx0, v0p[0]); v0p[1] = ffma2(w0p, xx1, v0p[1]);
        v0p[2] = ffma2(w0p, xx2, v0p[2]); v0p[3] = ffma2(w0p, xx3, v0p[3]);
        v0p[4] = ffma2(w0p, xx4, v0p[4]);
        v1p[0] = ffma2(w1p, xx0, v1p[0]); v1p[1] = ffma2(w1p, xx1, v1p[1]);
        v1p[2] = ffma2(w1p, xx2, v1p[2]); v1p[3] = ffma2(w1p, xx3, v1p[3]);
        v1p[4] = ffma2(w1p, xx4, v1p[4]);
        u0p[0] = ffma2(d0p, xx0, u0p[0]); u0p[1] = ffma2(d0p, xx1, u0p[1]);
        u0p[2] = ffma2(d0p, xx2, u0p[2]); u0p[3] = ffma2(d0p, xx3, u0p[3]);
        u0p[4] = ffma2(d0p, xx4, u0p[4]);
        u1p[0] = ffma2(d1p, xx0, u1p[0]); u1p[1] = ffma2(d1p, xx1, u1p[1]);
        u1p[2] = ffma2(d1p, xx2, u1p[2]); u1p[3] = ffma2(d1p, xx3, u1p[3]);
        u1p[4] = ffma2(d1p, xx4, u1p[4]);
    }

    // unpack scores1 and v; stash xq rows to shared (pairs are contiguous)
    float s1[9], v0[9], v1[9];
#pragma unroll
    for (int j = 0; j < 4; j++) {
        float2 f;
        f = unpack2(s1p[j]); s1[2 * j] = f.x; s1[2 * j + 1] = f.y;
        f = unpack2(v0p[j]); v0[2 * j] = f.x; v0[2 * j + 1] = f.y;
        f = unpack2(v1p[j]); v1[2 * j] = f.x; v1[2 * j + 1] = f.y;
    }
    s1[8] = unpack2(s1p[4]).x;
    v0[8] = unpack2(v0p[4]).x;
    v1[8] = unpack2(v1p[4]).x;
    {
        ull* q0 = (ull*)(xq + lane * 10);
        ull* q1 = (ull*)(xq + (lane + 32) * 10);
#pragma unroll
        for (int j = 0; j < 5; j++) { q0[j] = u0p[j]; q1[j] = u1p[j]; }
    }

    // softmax over pos (lane = ht) -> attn1 to shared (at == lp region)
    {
        float mx = s1[0];
#pragma unroll
        for (int p = 1; p < 9; p++) mx = fmaxf(mx, s1[p]);
        float sum = 0.f;
#pragma unroll
        for (int p = 0; p < 9; p++) { s1[p] = __expf(s1[p] - mx); sum += s1[p]; }
        float inv = 1.0f / sum;
#pragma unroll
        for (int p = 0; p < 9; p++) at[lane * 9 + p] = s1[p] * inv;
    }
    __syncwarp();

    // lt[h,t,d] = attn1 @ v + q   (lane owns channels lane, lane+32)
    const int h0 = lane >> 3;
    float lt0[4], lt1[4];
#pragma unroll
    for (int t = 0; t < 4; t++) {
        float a0 = ss[S_Q + lane * 4 + t];
        float a1 = ss[S_Q + (lane + 32) * 4 + t];
        const float* r0 = at + (h0 * 4 + t) * 9;
        const float* r1 = at + ((h0 + 4) * 4 + t) * 9;
#pragma unroll
        for (int p = 0; p < 9; p++) {
            a0 = fmaf(r0[p], v0[p], a0);
            a1 = fmaf(r1[p], v1[p], a1);
        }
        lt0[t] = a0; lt1[t] = a1;
    }
    __syncwarp();     // all lanes done reading attn1 before lp overwrite

    // spectral basis mixing via angle-addition recurrence -> lp[ch*5+t]
#pragma unroll
    for (int t = 0; t < 4; t++) {
        float base0 = lt0[t] * (float)(CUDART_PI / 12.0);
        float base1 = lt1[t] * (float)(CUDART_PI / 12.0);
        float s0, c0, sB, cB;
        __sincosf(base0, &s0, &c0);
        __sincosf(base1, &sB, &cB);
        float acc0 = ss[S_WT + 12 * 64 + lane];        // m=0: sin=0, cos=1
        float acc1 = ss[S_WT + 12 * 64 + lane + 32];
        float sa = s0, ca = c0, sb = sB, cb = cB;
#pragma unroll
        for (int m = 1; m < 12; m++) {
            acc0 = fmaf(sa, ss[S_WT + m * 64 + lane],
                   fmaf(ca, ss[S_WT + (12 + m) * 64 + lane], acc0));
            acc1 = fmaf(sb, ss[S_WT + m * 64 + lane + 32],
                   fmaf(cb, ss[S_WT + (12 + m) * 64 + lane + 32], acc1));
            float ns = fmaf(sa, c0,  ca * s0);
            float nc = fmaf(ca, c0, -sa * s0);
            sa = ns; ca = nc;
            float ms = fmaf(sb, cB,  cb * sB);
            float mc = fmaf(cb, cB, -sb * sB);
            sb = ms; cb = mc;
        }
        lp[lane * 5 + t]        = lt0[t] + acc0;
        lp[(lane + 32) * 5 + t] = lt1[t] + acc1;
    }
    __syncwarp();

    // ========= decoder attention (72 items = h x pos) =========
#pragma unroll
    for (int k = 0; k < 3; k++) {
        int item = lane + 32 * k;
        if (item < 72) {
            int h = item / 9, pos = item - h * 9;
            float sc[4] = {0.f, 0.f, 0.f, 0.f};
#pragma unroll
            for (int d = 0; d < 8; d++) {
                float xv = xq[(h * 8 + d) * 10 + pos];
                const float* lr = lp + (h * 8 + d) * 5;
#pragma unroll
                for (int t = 0; t < 4; t++) sc[t] = fmaf(xv, lr[t], sc[t]);
            }
            float m2 = fmaxf(fmaxf(sc[0], sc[1]), fmaxf(sc[2], sc[3]));
            float es = 0.f;
#pragma unroll
            for (int t = 0; t < 4; t++) { sc[t] = __expf(sc[t] - m2); es += sc[t]; }
            float inv = 1.0f / es;
#pragma unroll
            for (int t = 0; t < 4; t++) sc[t] *= inv;
#pragma unroll
            for (int d = 0; d < 8; d++) {
                const float* lr = lp + (h * 8 + d) * 5;
                float o = 0.f;
#pragma unroll
                for (int t = 0; t < 4; t++) o = fmaf(sc[t], lr[t], o);
                xq[(h * 8 + d) * 10 + pos] = o;   // own (h,pos) slots only
            }
        }
    }
    __syncthreads();

    // strength-reduced un-patchify store with residual
    if (cg < 3) {
        float* dst = out + ((size_t)(b * 64 + cg) * Hn + hp * 3 + p0m) * Wn
                         + wblk * 24 + col;
        const float* sq = sxq + wl * XQS + cg * 10 + p0m * 3 + p1m;
        const float* sp = sxp + wl * XPS + cg * 12 + p0m * 3 + p1m;
#pragma unroll
        for (int c = cg; c < 64; c += 3) {
            *dst = *sq + *sp;
            dst += 3 * Hn * Wn;
            sq  += 30;
            sp  += 36;
        }
    }
}

extern "C" void kernel_launch(void* const* d_in, const int* in_sizes, int n_in,
                              void* d_out, int out_size) {
    const float* x       = (const float*)d_in[0];
    const float* latent  = (const float*)d_in[1];
    const float* weights = (const float*)d_in[2];
    const float* enc_w   = (const float*)d_in[3];
    const float* enc_b   = (const float*)d_in[4];
    const float* dec_w   = (const float*)d_in[5];
    const float* dec_b   = (const float*)d_in[6];
    float* out = (float*)d_out;

    cudaFuncSetAttribute(nsb_kernel,
                         cudaFuncAttributeMaxDynamicSharedMemorySize, SMEM_B);

    setup_kernel<<<1, 256>>>(latent, weights, enc_w, enc_b, dec_w, dec_b);
    nsb_kernel<<<GRID, NT, SMEM_B>>>(x, out);
}